// round 3
// baseline (speedup 1.0000x reference)
#include <cuda_runtime.h>

#define Nn 32
#define Cc 512
#define Hh 64
#define Ww 64
#define CBn 32          // bottleneck channels C/R
#define Sp (Hh*Ww)      // 4096 spatial per channel
#define EPSv 1e-5f
#define GRP 8           // batch group size for L2 blocking (8 * 8MB = 64MB < 126MB L2)

// Scratch (allocation-free rule: __device__ globals)
__device__ float g_attn[Nn * Sp];      // logits -> attn (in place)
__device__ float g_ctx[Nn * Cc];       // pooled context
__device__ float g_delta[Nn * Cc];     // per-(n,c) broadcast add term
__device__ int   g_cnt_log[Nn];        // per-n ticket for logits->softmax (self-resetting)
__device__ int   g_cnt_ctx[Nn];        // per-n ticket for ctx->mlp (self-resetting)

// ---------------------------------------------------------------------------
// K1: logits[n,h,w] = sum_c x[n,c,h,w]*wk_w[c] + wk_b, then the LAST block of
// each n (ticket) runs softmax over H in place. block=(n,h), 256 threads.
// ---------------------------------------------------------------------------
__global__ void k_logits(const float* __restrict__ x,
                         const float* __restrict__ wk_w,
                         const float* __restrict__ wk_b, int n0) {
    int n = n0 + (blockIdx.x >> 6);   // / Hh
    int h = blockIdx.x & 63;          // % Hh
    int tid = threadIdx.x;            // 0..255
    int wq = tid & 15;                // float4 index over w (w = wq*4)
    int cc = tid >> 4;                // c-chunk 0..15 (32 channels each)

    const float4* xp = (const float4*)(x + (((size_t)(n * Cc + cc * 32)) * Hh + h) * Ww) + wq;
    const size_t cstride4 = Sp / 4;   // float4 stride between channels = 1024

    float4 acc = make_float4(0.f, 0.f, 0.f, 0.f);
#pragma unroll
    for (int i = 0; i < 32; i++) {
        float wv = __ldg(&wk_w[cc * 32 + i]);
        float4 v = __ldg(xp + (size_t)i * cstride4);
        acc.x += v.x * wv; acc.y += v.y * wv;
        acc.z += v.z * wv; acc.w += v.w * wv;
    }

    __shared__ float sred[16][Ww];
    sred[cc][wq * 4 + 0] = acc.x;
    sred[cc][wq * 4 + 1] = acc.y;
    sred[cc][wq * 4 + 2] = acc.z;
    sred[cc][wq * 4 + 3] = acc.w;
    __syncthreads();

    if (tid < Ww) {
        float s = 0.f;
#pragma unroll
        for (int k = 0; k < 16; k++) s += sred[k][tid];
        g_attn[((size_t)n * Hh + h) * Ww + tid] = s + __ldg(&wk_b[0]);
    }

    // ---- ticket: last (n,h) block performs softmax over H for this n ----
    __shared__ int slast;
    __threadfence();                  // make logits row visible before ticket
    __syncthreads();                  // row write done by tid<64 before ticket
    if (tid == 0) {
        int v = atomicAdd(&g_cnt_log[n], 1);
        slast = (v == Hh - 1);
        if (slast) g_cnt_log[n] = 0;  // self-reset for next graph replay
    }
    __syncthreads();
    if (slast && tid < Ww) {
        __threadfence();              // acquire other blocks' rows
        float* L = g_attn + (size_t)n * Sp;
        int w = tid;
        float vals[Hh];
        float m = -1e30f;
#pragma unroll
        for (int hh = 0; hh < Hh; hh++) {
            vals[hh] = L[hh * Ww + w];
            m = fmaxf(m, vals[hh]);
        }
        float sum = 0.f;
#pragma unroll
        for (int hh = 0; hh < Hh; hh++) {
            vals[hh] = __expf(vals[hh] - m);
            sum += vals[hh];
        }
        float inv = 1.f / sum;
#pragma unroll
        for (int hh = 0; hh < Hh; hh++) L[hh * Ww + w] = vals[hh] * inv;
    }
}

// ---------------------------------------------------------------------------
// K2: ctx[n,c] = sum_{h,w} x[n,c,h,w] * attn[n,h,w]   (x hits L2)
// then LAST block of each n (ticket) runs the bottleneck MLP inline:
//   v = ctx @ wv1^T ; LayerNorm(32) ; ReLU ; delta = v @ wv2^T
// block per (n,c); 128 threads.
// ---------------------------------------------------------------------------
__global__ void k_ctx(const float* __restrict__ x,
                      const float* __restrict__ wv1,
                      const float* __restrict__ ln_g,
                      const float* __restrict__ ln_b,
                      const float* __restrict__ wv2, int n0) {
    int n = n0 + (blockIdx.x >> 9);   // / Cc
    int c = blockIdx.x & 511;         // % Cc
    int tid = threadIdx.x;            // 0..127
    int lane = tid & 31;
    int wid = tid >> 5;               // 0..3

    const float4* xp = (const float4*)(x + ((size_t)n * Cc + c) * Sp);
    const float4* ap = (const float4*)(g_attn + (size_t)n * Sp);

    float acc = 0.f;
#pragma unroll
    for (int i = 0; i < 8; i++) {
        float4 xv = __ldg(xp + tid + i * 128);
        float4 av = __ldg(ap + tid + i * 128);
        acc += xv.x * av.x + xv.y * av.y + xv.z * av.z + xv.w * av.w;
    }

    __shared__ float s[128];
    s[tid] = acc;
    __syncthreads();
    if (tid < 64) s[tid] += s[tid + 64];
    __syncthreads();
    if (tid < 32) {
        float v = s[tid] + s[tid + 32];
#pragma unroll
        for (int o = 16; o; o >>= 1) v += __shfl_xor_sync(0xffffffffu, v, o);
        if (tid == 0) g_ctx[(size_t)n * Cc + c] = v;
    }

    // ---- ticket: last (n,c) block performs the MLP for this n ----
    __shared__ int slast;
    __threadfence();
    __syncthreads();
    if (tid == 0) {
        int v = atomicAdd(&g_cnt_ctx[n], 1);
        slast = (v == Cc - 1);
        if (slast) g_cnt_ctx[n] = 0;  // self-reset for next graph replay
    }
    __syncthreads();
    if (!slast) return;

    __threadfence();                  // acquire all ctx values for this n
    __shared__ float sctx[Cc];
    __shared__ float sv[CBn];
#pragma unroll
    for (int k = 0; k < Cc / 128; k++) sctx[tid + k * 128] = g_ctx[(size_t)n * Cc + tid + k * 128];
    __syncthreads();

    // v_j: 4 warps x 8 j's each
#pragma unroll
    for (int jj = 0; jj < 8; jj++) {
        int j = wid * 8 + jj;
        const float* w1 = wv1 + (size_t)j * Cc;
        float a = 0.f;
#pragma unroll
        for (int k = 0; k < Cc / 32; k++) {
            int idx = lane + k * 32;
            a += sctx[idx] * __ldg(&w1[idx]);
        }
#pragma unroll
        for (int o = 16; o; o >>= 1) a += __shfl_xor_sync(0xffffffffu, a, o);
        if (lane == 0) sv[j] = a;
    }
    __syncthreads();

    // LayerNorm + ReLU over 32 values (warp 0)
    if (wid == 0) {
        float v = sv[lane];
        float mu = v;
#pragma unroll
        for (int o = 16; o; o >>= 1) mu += __shfl_xor_sync(0xffffffffu, mu, o);
        mu *= (1.f / 32.f);
        float d = v - mu;
        float var = d * d;
#pragma unroll
        for (int o = 16; o; o >>= 1) var += __shfl_xor_sync(0xffffffffu, var, o);
        var *= (1.f / 32.f);
        v = d * rsqrtf(var + EPSv) * __ldg(&ln_g[lane]) + __ldg(&ln_b[lane]);
        sv[lane] = fmaxf(v, 0.f);
    }
    __syncthreads();

    // delta[n,c2] for all 512 channels: 4 per thread
#pragma unroll
    for (int k = 0; k < Cc / 128; k++) {
        int c2 = tid + k * 128;
        const float* w2 = wv2 + (size_t)c2 * CBn;
        float sdot = 0.f;
#pragma unroll
        for (int j = 0; j < CBn; j++) sdot += sv[j] * __ldg(&w2[j]);
        g_delta[(size_t)n * Cc + c2] = sdot;
    }
}

// ---------------------------------------------------------------------------
// K3: out[n,c,h,w] = x[n,c,h,w] + delta[n,c]   (x hits L2; write streams out)
// Pointers pre-offset to the group base.
// ---------------------------------------------------------------------------
__global__ void k_add(const float* __restrict__ x, float* __restrict__ out,
                      const float* __restrict__ delta) {
    size_t i = (size_t)blockIdx.x * blockDim.x + threadIdx.x;  // float4 index
    float4 v = __ldg((const float4*)x + i);
    int nc = (int)(i >> 10);          // (i*4)/4096
    float d = __ldg(&delta[nc]);
    float4 o = make_float4(v.x + d, v.y + d, v.z + d, v.w + d);
    ((float4*)out)[i] = o;
}

// ---------------------------------------------------------------------------
extern "C" void kernel_launch(void* const* d_in, const int* in_sizes, int n_in,
                              void* d_out, int out_size) {
    const float* x    = (const float*)d_in[0];
    const float* wk_w = (const float*)d_in[1];
    const float* wk_b = (const float*)d_in[2];
    const float* wv1  = (const float*)d_in[3];
    const float* ln_g = (const float*)d_in[4];
    const float* ln_b = (const float*)d_in[5];
    const float* wv2  = (const float*)d_in[6];
    float* out = (float*)d_out;

    float* d_delta = nullptr;
    cudaGetSymbolAddress((void**)&d_delta, g_delta);

    const size_t grp_elems = (size_t)GRP * Cc * Sp;       // 16M floats
    const unsigned add_blocks = (unsigned)(grp_elems / 4 / 256);

    for (int n0 = 0; n0 < Nn; n0 += GRP) {
        size_t xoff = (size_t)n0 * Cc * Sp;
        k_logits<<<GRP * Hh, 256>>>(x, wk_w, wk_b, n0);
        k_ctx<<<GRP * Cc, 128>>>(x, wv1, ln_g, ln_b, wv2, n0);
        k_add<<<add_blocks, 256>>>(x + xoff, out + xoff, d_delta + (size_t)n0 * Cc);
    }
}

// round 4
// speedup vs baseline: 1.1597x; 1.1597x over previous
#include <cuda_runtime.h>

#define Nn 32
#define Cc 512
#define Hh 64
#define Ww 64
#define CBn 32          // bottleneck channels C/R
#define Sp (Hh*Ww)      // 4096 spatial per channel
#define EPSv 1e-5f
#define GRP 4           // batch group size: 4 * 8MB = 32MB; 2 groups in flight = 64MB < L2
#define NSTREAMS 2

// Scratch (allocation-free rule: __device__ globals). Indexed by global n ->
// disjoint across concurrently-running groups.
__device__ float g_attn[Nn * Sp];      // logits -> attn (in place)
__device__ float g_ctx[Nn * Cc];       // pooled context
__device__ float g_delta[Nn * Cc];     // per-(n,c) broadcast add term

// ---------------------------------------------------------------------------
// K1: logits[n,h,w] = sum_c x[n,c,h,w] * wk_w[c] + wk_b
// block = (n,h) row; 256 threads = 16 w-float4 groups x 16 c-chunks of 32
// ---------------------------------------------------------------------------
__global__ void __launch_bounds__(256, 6)
k_logits(const float* __restrict__ x,
         const float* __restrict__ wk_w,
         const float* __restrict__ wk_b, int n0) {
    int n = n0 + (blockIdx.x >> 6);   // / Hh
    int h = blockIdx.x & 63;          // % Hh
    int tid = threadIdx.x;            // 0..255
    int wq = tid & 15;                // float4 index over w (w = wq*4)
    int cc = tid >> 4;                // c-chunk 0..15 (32 channels each)

    const float4* xp = (const float4*)(x + (((size_t)(n * Cc + cc * 32)) * Hh + h) * Ww) + wq;
    const size_t cstride4 = Sp / 4;   // float4 stride between channels = 1024

    float4 acc = make_float4(0.f, 0.f, 0.f, 0.f);
#pragma unroll 8
    for (int i = 0; i < 32; i++) {
        float wv = __ldg(&wk_w[cc * 32 + i]);
        float4 v = __ldg(xp + (size_t)i * cstride4);
        acc.x += v.x * wv; acc.y += v.y * wv;
        acc.z += v.z * wv; acc.w += v.w * wv;
    }

    __shared__ float sred[16][Ww];
    sred[cc][wq * 4 + 0] = acc.x;
    sred[cc][wq * 4 + 1] = acc.y;
    sred[cc][wq * 4 + 2] = acc.z;
    sred[cc][wq * 4 + 3] = acc.w;
    __syncthreads();

    if (tid < Ww) {
        float s = 0.f;
#pragma unroll
        for (int k = 0; k < 16; k++) s += sred[k][tid];
        g_attn[((size_t)n * Hh + h) * Ww + tid] = s + __ldg(&wk_b[0]);
    }
}

// ---------------------------------------------------------------------------
// K2: softmax over H (axis=1) for each (n, w), in place on g_attn. Tiny.
// ---------------------------------------------------------------------------
__global__ void k_softmax(int n0) {
    int n = n0 + blockIdx.x;
    int w = threadIdx.x;              // 0..63
    float* L = g_attn + (size_t)n * Sp;

    float vals[Hh];
    float m = -1e30f;
#pragma unroll
    for (int h = 0; h < Hh; h++) {
        vals[h] = L[h * Ww + w];
        m = fmaxf(m, vals[h]);
    }
    float sum = 0.f;
#pragma unroll
    for (int h = 0; h < Hh; h++) {
        vals[h] = __expf(vals[h] - m);
        sum += vals[h];
    }
    float inv = 1.f / sum;
#pragma unroll
    for (int h = 0; h < Hh; h++) L[h * Ww + w] = vals[h] * inv;
}

// ---------------------------------------------------------------------------
// K3: ctx[n,c] = sum_{h,w} x[n,c,h,w] * attn[n,h,w]   (x hits L2)
// block per (n,c); 128 threads reduce 4096 contiguous floats (float4).
// ---------------------------------------------------------------------------
__global__ void k_ctx(const float* __restrict__ x, int n0) {
    int n = n0 + (blockIdx.x >> 9);   // / Cc
    int c = blockIdx.x & 511;         // % Cc
    int tid = threadIdx.x;            // 0..127

    const float4* xp = (const float4*)(x + ((size_t)n * Cc + c) * Sp);
    const float4* ap = (const float4*)(g_attn + (size_t)n * Sp);

    float acc = 0.f;
#pragma unroll
    for (int i = 0; i < 8; i++) {
        float4 xv = __ldg(xp + tid + i * 128);
        float4 av = __ldg(ap + tid + i * 128);
        acc += xv.x * av.x + xv.y * av.y + xv.z * av.z + xv.w * av.w;
    }

    __shared__ float s[128];
    s[tid] = acc;
    __syncthreads();
    if (tid < 64) s[tid] += s[tid + 64];
    __syncthreads();
    if (tid < 32) {
        float v = s[tid] + s[tid + 32];
#pragma unroll
        for (int o = 16; o; o >>= 1) v += __shfl_xor_sync(0xffffffffu, v, o);
        if (tid == 0) g_ctx[(size_t)n * Cc + c] = v;
    }
}

// ---------------------------------------------------------------------------
// K4: bottleneck MLP, one block per n, 1024 threads.
//   v_j = dot(ctx[n,:], wv1[j,:])  -- warp j
//   LayerNorm+ReLU over 32 v's     -- warp 0
//   delta[n,c] = dot(v, wv2[c,:])  -- threads 0..511
// ---------------------------------------------------------------------------
__global__ void k_mlp(const float* __restrict__ wv1,
                      const float* __restrict__ ln_g,
                      const float* __restrict__ ln_b,
                      const float* __restrict__ wv2, int n0) {
    int n = n0 + blockIdx.x;
    int tid = threadIdx.x;            // 0..1023
    int wid = tid >> 5;               // warp = bottleneck channel j
    int lane = tid & 31;

    __shared__ float sctx[Cc];
    __shared__ float sv[CBn];

    if (tid < Cc) sctx[tid] = g_ctx[(size_t)n * Cc + tid];
    __syncthreads();

    float acc = 0.f;
    const float* w1 = wv1 + (size_t)wid * Cc;
#pragma unroll
    for (int k = 0; k < Cc / 32; k++) {
        int idx = lane + k * 32;
        acc += sctx[idx] * __ldg(&w1[idx]);
    }
#pragma unroll
    for (int o = 16; o; o >>= 1) acc += __shfl_xor_sync(0xffffffffu, acc, o);
    if (lane == 0) sv[wid] = acc;
    __syncthreads();

    if (wid == 0) {
        float v = sv[lane];
        float mu = v;
#pragma unroll
        for (int o = 16; o; o >>= 1) mu += __shfl_xor_sync(0xffffffffu, mu, o);
        mu *= (1.f / 32.f);
        float d = v - mu;
        float var = d * d;
#pragma unroll
        for (int o = 16; o; o >>= 1) var += __shfl_xor_sync(0xffffffffu, var, o);
        var *= (1.f / 32.f);
        v = d * rsqrtf(var + EPSv) * __ldg(&ln_g[lane]) + __ldg(&ln_b[lane]);
        sv[lane] = fmaxf(v, 0.f);
    }
    __syncthreads();

    if (tid < Cc) {
        const float* w2 = wv2 + (size_t)tid * CBn;
        float s = 0.f;
#pragma unroll
        for (int j = 0; j < CBn; j++) s += sv[j] * __ldg(&w2[j]);
        g_delta[(size_t)n * Cc + tid] = s;
    }
}

// ---------------------------------------------------------------------------
// K5: out = x + delta[n,c]   (x hits L2; write streams out). Pointers are
// pre-offset to the group base.
// ---------------------------------------------------------------------------
__global__ void k_add(const float* __restrict__ x, float* __restrict__ out,
                      const float* __restrict__ delta) {
    size_t i = (size_t)blockIdx.x * blockDim.x + threadIdx.x;  // float4 index
    float4 v = __ldg((const float4*)x + i);
    int nc = (int)(i >> 10);          // (i*4)/4096
    float d = __ldg(&delta[nc]);
    float4 o = make_float4(v.x + d, v.y + d, v.z + d, v.w + d);
    ((float4*)out)[i] = o;
}

// ---------------------------------------------------------------------------
extern "C" void kernel_launch(void* const* d_in, const int* in_sizes, int n_in,
                              void* d_out, int out_size) {
    const float* x    = (const float*)d_in[0];
    const float* wk_w = (const float*)d_in[1];
    const float* wk_b = (const float*)d_in[2];
    const float* wv1  = (const float*)d_in[3];
    const float* ln_g = (const float*)d_in[4];
    const float* ln_b = (const float*)d_in[5];
    const float* wv2  = (const float*)d_in[6];
    float* out = (float*)d_out;

    float* d_delta = nullptr;
    cudaGetSymbolAddress((void**)&d_delta, g_delta);

    // One-time side-stream / event setup (infrastructure only; every call
    // launches the full, identical set of kernels).
    static cudaStream_t streams[NSTREAMS];
    static cudaEvent_t ev_root, ev_done[NSTREAMS];
    static bool res_init = false;
    if (!res_init) {
        for (int i = 0; i < NSTREAMS; i++) {
            cudaStreamCreateWithFlags(&streams[i], cudaStreamNonBlocking);
            cudaEventCreateWithFlags(&ev_done[i], cudaEventDisableTiming);
        }
        cudaEventCreateWithFlags(&ev_root, cudaEventDisableTiming);
        res_init = true;
    }

    const size_t grp_elems = (size_t)GRP * Cc * Sp;       // 8M floats
    const unsigned add_blocks = (unsigned)(grp_elems / 4 / 256);

    // Fork the capture stream (legacy stream 0) into NSTREAMS side streams.
    cudaEventRecord(ev_root, 0);
    for (int i = 0; i < NSTREAMS; i++)
        cudaStreamWaitEvent(streams[i], ev_root, 0);

    // Independent per-group pipelines, round-robin across streams.
    for (int g = 0; g < Nn / GRP; g++) {
        int n0 = g * GRP;
        cudaStream_t st = streams[g % NSTREAMS];
        size_t xoff = (size_t)n0 * Cc * Sp;
        k_logits<<<GRP * Hh, 256, 0, st>>>(x, wk_w, wk_b, n0);
        k_softmax<<<GRP, Ww, 0, st>>>(n0);
        k_ctx<<<GRP * Cc, 128, 0, st>>>(x, n0);
        k_mlp<<<GRP, 1024, 0, st>>>(wv1, ln_g, ln_b, wv2, n0);
        k_add<<<add_blocks, 256, 0, st>>>(x + xoff, out + xoff,
                                          d_delta + (size_t)n0 * Cc);
    }

    // Join back into the capture stream.
    for (int i = 0; i < NSTREAMS; i++) {
        cudaEventRecord(ev_done[i], streams[i]);
        cudaStreamWaitEvent(0, ev_done[i], 0);
    }
}

// round 5
// speedup vs baseline: 1.3533x; 1.1669x over previous
#include <cuda_runtime.h>

#define Nn 32
#define Cc 512
#define Hh 64
#define Ww 64
#define CBn 32          // bottleneck channels C/R
#define Sp (Hh*Ww)      // 4096 spatial per channel
#define EPSv 1e-5f
#define GRP 4           // 4 * 8MB = 32MB per group; 3 in flight = 96MB < 126MB L2
#define NSTREAMS 3

// Scratch (allocation-free rule: __device__ globals). Indexed by global n ->
// disjoint across concurrently-running groups.
__device__ float g_attn[Nn * Sp];      // logits -> attn (in place)
__device__ float g_ctx[Nn * Cc];       // pooled context
__device__ float g_delta[Nn * Cc];     // per-(n,c) broadcast add term

// ---------------------------------------------------------------------------
// K1: logits[n,h,w] = sum_c x[n,c,h,w] * wk_w[c] + wk_b
// block = (n,h) row; 256 threads = 16 w-float4 groups x 16 c-chunks of 32
// ---------------------------------------------------------------------------
__global__ void __launch_bounds__(256, 6)
k_logits(const float* __restrict__ x,
         const float* __restrict__ wk_w,
         const float* __restrict__ wk_b, int n0) {
    int n = n0 + (blockIdx.x >> 6);   // / Hh
    int h = blockIdx.x & 63;          // % Hh
    int tid = threadIdx.x;            // 0..255
    int wq = tid & 15;                // float4 index over w (w = wq*4)
    int cc = tid >> 4;                // c-chunk 0..15 (32 channels each)

    const float4* xp = (const float4*)(x + (((size_t)(n * Cc + cc * 32)) * Hh + h) * Ww) + wq;
    const size_t cstride4 = Sp / 4;   // float4 stride between channels = 1024

    float4 acc = make_float4(0.f, 0.f, 0.f, 0.f);
#pragma unroll 8
    for (int i = 0; i < 32; i++) {
        float wv = __ldg(&wk_w[cc * 32 + i]);
        float4 v = __ldg(xp + (size_t)i * cstride4);
        acc.x += v.x * wv; acc.y += v.y * wv;
        acc.z += v.z * wv; acc.w += v.w * wv;
    }

    __shared__ float sred[16][Ww];
    sred[cc][wq * 4 + 0] = acc.x;
    sred[cc][wq * 4 + 1] = acc.y;
    sred[cc][wq * 4 + 2] = acc.z;
    sred[cc][wq * 4 + 3] = acc.w;
    __syncthreads();

    if (tid < Ww) {
        float s = 0.f;
#pragma unroll
        for (int k = 0; k < 16; k++) s += sred[k][tid];
        g_attn[((size_t)n * Hh + h) * Ww + tid] = s + __ldg(&wk_b[0]);
    }
}

// ---------------------------------------------------------------------------
// K2: softmax over H (axis=1) for each (n, w), in place on g_attn. Tiny.
// ---------------------------------------------------------------------------
__global__ void k_softmax(int n0) {
    int n = n0 + blockIdx.x;
    int w = threadIdx.x;              // 0..63
    float* L = g_attn + (size_t)n * Sp;

    float vals[Hh];
    float m = -1e30f;
#pragma unroll
    for (int h = 0; h < Hh; h++) {
        vals[h] = L[h * Ww + w];
        m = fmaxf(m, vals[h]);
    }
    float sum = 0.f;
#pragma unroll
    for (int h = 0; h < Hh; h++) {
        vals[h] = __expf(vals[h] - m);
        sum += vals[h];
    }
    float inv = 1.f / sum;
#pragma unroll
    for (int h = 0; h < Hh; h++) L[h * Ww + w] = vals[h] * inv;
}

// ---------------------------------------------------------------------------
// K3: ctx[n,c] = sum_{h,w} x[n,c,h,w] * attn[n,h,w]   (x hits L2)
// block per (n,c); 128 threads reduce 4096 contiguous floats (float4).
// ---------------------------------------------------------------------------
__global__ void k_ctx(const float* __restrict__ x, int n0) {
    int n = n0 + (blockIdx.x >> 9);   // / Cc
    int c = blockIdx.x & 511;         // % Cc
    int tid = threadIdx.x;            // 0..127

    const float4* xp = (const float4*)(x + ((size_t)n * Cc + c) * Sp);
    const float4* ap = (const float4*)(g_attn + (size_t)n * Sp);

    float acc = 0.f;
#pragma unroll
    for (int i = 0; i < 8; i++) {
        float4 xv = __ldg(xp + tid + i * 128);
        float4 av = __ldg(ap + tid + i * 128);
        acc += xv.x * av.x + xv.y * av.y + xv.z * av.z + xv.w * av.w;
    }

    __shared__ float s[128];
    s[tid] = acc;
    __syncthreads();
    if (tid < 64) s[tid] += s[tid + 64];
    __syncthreads();
    if (tid < 32) {
        float v = s[tid] + s[tid + 32];
#pragma unroll
        for (int o = 16; o; o >>= 1) v += __shfl_xor_sync(0xffffffffu, v, o);
        if (tid == 0) g_ctx[(size_t)n * Cc + c] = v;
    }
}

// ---------------------------------------------------------------------------
// K4: bottleneck MLP, one block per n, 1024 threads, smem-staged weights.
// Dynamic smem layout (floats):
//   [0      : 16384)  wv1  (32 x 512, row-major, as in gmem)
//   [16384  : 32768)  wv2T (32 x 512: wv2 transposed -> conflict-free GEMV2)
//   [32768  : 33280)  ctx
//   [33280  : 33312)  v / sv
// ---------------------------------------------------------------------------
__global__ void k_mlp(const float* __restrict__ wv1,
                      const float* __restrict__ ln_g,
                      const float* __restrict__ ln_b,
                      const float* __restrict__ wv2, int n0) {
    extern __shared__ float sm[];
    float* s_w1  = sm;             // 16384
    float* s_w2t = sm + 16384;     // 16384
    float* sctx  = sm + 32768;     // 512
    float* sv    = sm + 33280;     // 32

    int n = n0 + blockIdx.x;
    int tid = threadIdx.x;            // 0..1023
    int wid = tid >> 5;
    int lane = tid & 31;

    // stage wv1: 4096 float4, coalesced, same layout
    const float4* w1v = (const float4*)wv1;
#pragma unroll
    for (int i = 0; i < 4; i++) {
        int f = tid + i * 1024;
        ((float4*)s_w1)[f] = __ldg(w1v + f);
    }
    // stage wv2 transposed: wv2 is (512 c, 32 j) row-major
    const float4* w2v = (const float4*)wv2;
#pragma unroll
    for (int i = 0; i < 4; i++) {
        int f = tid + i * 1024;       // flat float4 idx: c = f>>3, j4 = f&7
        int c = f >> 3;
        int j = (f & 7) * 4;
        float4 v = __ldg(w2v + f);
        s_w2t[(j + 0) * Cc + c] = v.x;
        s_w2t[(j + 1) * Cc + c] = v.y;
        s_w2t[(j + 2) * Cc + c] = v.z;
        s_w2t[(j + 3) * Cc + c] = v.w;
    }
    // stage ctx
    if (tid < Cc / 4) {
        ((float4*)sctx)[tid] = __ldg((const float4*)(g_ctx + (size_t)n * Cc) + tid);
    }
    __syncthreads();

    // GEMV1: warp j computes v_j = dot(ctx, wv1[j,:]) from smem
    float acc = 0.f;
    const float* w1r = s_w1 + wid * Cc;
#pragma unroll
    for (int k = 0; k < Cc / 32; k++) {
        int idx = lane + k * 32;
        acc += sctx[idx] * w1r[idx];
    }
#pragma unroll
    for (int o = 16; o; o >>= 1) acc += __shfl_xor_sync(0xffffffffu, acc, o);
    if (lane == 0) sv[wid] = acc;
    __syncthreads();

    // LayerNorm + ReLU over 32 values (warp 0)
    if (wid == 0) {
        float v = sv[lane];
        float mu = v;
#pragma unroll
        for (int o = 16; o; o >>= 1) mu += __shfl_xor_sync(0xffffffffu, mu, o);
        mu *= (1.f / 32.f);
        float d = v - mu;
        float var = d * d;
#pragma unroll
        for (int o = 16; o; o >>= 1) var += __shfl_xor_sync(0xffffffffu, var, o);
        var *= (1.f / 32.f);
        v = d * rsqrtf(var + EPSv) * __ldg(&ln_g[lane]) + __ldg(&ln_b[lane]);
        sv[lane] = fmaxf(v, 0.f);
    }
    __syncthreads();

    // GEMV2: thread c computes delta[n,c] = dot(sv, wv2[c,:]) via s_w2t
    if (tid < Cc) {
        float s = 0.f;
#pragma unroll
        for (int j = 0; j < CBn; j++) s += sv[j] * s_w2t[j * Cc + tid];
        g_delta[(size_t)n * Cc + tid] = s;
    }
}

// ---------------------------------------------------------------------------
// K5: out = x + delta[n,c]   (x hits L2; write streams out). Pointers are
// pre-offset to the group base.
// ---------------------------------------------------------------------------
__global__ void k_add(const float* __restrict__ x, float* __restrict__ out,
                      const float* __restrict__ delta) {
    size_t i = (size_t)blockIdx.x * blockDim.x + threadIdx.x;  // float4 index
    float4 v = __ldg((const float4*)x + i);
    int nc = (int)(i >> 10);          // (i*4)/4096
    float d = __ldg(&delta[nc]);
    float4 o = make_float4(v.x + d, v.y + d, v.z + d, v.w + d);
    ((float4*)out)[i] = o;
}

// ---------------------------------------------------------------------------
extern "C" void kernel_launch(void* const* d_in, const int* in_sizes, int n_in,
                              void* d_out, int out_size) {
    const float* x    = (const float*)d_in[0];
    const float* wk_w = (const float*)d_in[1];
    const float* wk_b = (const float*)d_in[2];
    const float* wv1  = (const float*)d_in[3];
    const float* ln_g = (const float*)d_in[4];
    const float* ln_b = (const float*)d_in[5];
    const float* wv2  = (const float*)d_in[6];
    float* out = (float*)d_out;

    float* d_delta = nullptr;
    cudaGetSymbolAddress((void**)&d_delta, g_delta);

    static cudaStream_t streams[NSTREAMS];
    static cudaEvent_t ev_root, ev_done[NSTREAMS];
    static bool res_init = false;
    if (!res_init) {
        for (int i = 0; i < NSTREAMS; i++) {
            cudaStreamCreateWithFlags(&streams[i], cudaStreamNonBlocking);
            cudaEventCreateWithFlags(&ev_done[i], cudaEventDisableTiming);
        }
        cudaEventCreateWithFlags(&ev_root, cudaEventDisableTiming);
        cudaFuncSetAttribute(k_mlp, cudaFuncAttributeMaxDynamicSharedMemorySize,
                             (33312) * sizeof(float));
        res_init = true;
    }

    const size_t mlp_smem = 33312 * sizeof(float);   // ~130 KB
    const size_t grp_elems = (size_t)GRP * Cc * Sp;  // 8M floats
    const unsigned add_blocks = (unsigned)(grp_elems / 4 / 256);

    // Fork the capture stream into side streams.
    cudaEventRecord(ev_root, 0);
    for (int i = 0; i < NSTREAMS; i++)
        cudaStreamWaitEvent(streams[i], ev_root, 0);

    for (int g = 0; g < Nn / GRP; g++) {
        int n0 = g * GRP;
        cudaStream_t st = streams[g % NSTREAMS];
        size_t xoff = (size_t)n0 * Cc * Sp;
        k_logits<<<GRP * Hh, 256, 0, st>>>(x, wk_w, wk_b, n0);
        k_softmax<<<GRP, Ww, 0, st>>>(n0);
        k_ctx<<<GRP * Cc, 128, 0, st>>>(x, n0);
        k_mlp<<<GRP, 1024, mlp_smem, st>>>(wv1, ln_g, ln_b, wv2, n0);
        k_add<<<add_blocks, 256, 0, st>>>(x + xoff, out + xoff,
                                          d_delta + (size_t)n0 * Cc);
    }

    for (int i = 0; i < NSTREAMS; i++) {
        cudaEventRecord(ev_done[i], streams[i]);
        cudaStreamWaitEvent(0, ev_done[i], 0);
    }
}